// round 4
// baseline (speedup 1.0000x reference)
#include <cuda_runtime.h>
#include <cstdint>

// Problem constants
#define DDIM   768
#define BATCH  8
#define SLEN   2048
#define MTOT   (BATCH * SLEN)   // 16384

// GEMM tiling
#define BM 128
#define BN 128
#define BK 16
#define NTHREADS 256
#define KTILES (DDIM / BK)      // 48
#define BSTRIDE (BN + 8)        // 136 words: 136 mod 32 == 8 -> conflict-free B fragment reads

// Per-batch fused bias: bt + Vb  (Vb = (ac@Wa+ba)@Wv + bv)
__device__ float g_bias[BATCH][DDIM];

// ---------------------------------------------------------------------------
// Kernel A: tiny per-batch bias precompute.
// fa[j] = ba[j] + sum_k ac[b,k] * Wa[k,j]    (k < 16)
// g_bias[b][j] = bt[j] + bv[j] + sum_k fa[k] * Wv[k,j]
// ---------------------------------------------------------------------------
__global__ void bias_kernel(const float* __restrict__ ac,   // [B,16]
                            const float* __restrict__ Wa,   // [16,768]
                            const float* __restrict__ ba,   // [768]
                            const float* __restrict__ Wv,   // [768,768]
                            const float* __restrict__ bv,   // [768]
                            const float* __restrict__ bt)   // [768]
{
    int b = blockIdx.x;
    int j = threadIdx.x;             // 0..767
    __shared__ float fa[DDIM];
    __shared__ float a[16];
    if (j < 16) a[j] = ac[b * 16 + j];
    __syncthreads();

    float s = ba[j];
#pragma unroll
    for (int k = 0; k < 16; k++) s += a[k] * Wa[k * DDIM + j];
    fa[j] = s;
    __syncthreads();

    float v = bv[j];
    for (int k = 0; k < DDIM; k++) v += fa[k] * Wv[k * DDIM + j];
    g_bias[b][j] = v + bt[j];
}

// ---------------------------------------------------------------------------
// Kernel B: out[m, n] = X[m, :] @ Wt[:, n] + g_bias[m >> 11][n]
// tf32 tensor-core GEMM, mma.sync.m16n8k8, CTA tile 128x128x16,
// double-buffered smem with LDG->reg prefetch pipelined over the MMAs.
// ---------------------------------------------------------------------------
__device__ __forceinline__ unsigned f2tf32(float x) {
    unsigned r;
    asm("cvt.rna.tf32.f32 %0, %1;" : "=r"(r) : "f"(x));
    return r;
}

__device__ __forceinline__ void mma_tf32(float& d0, float& d1, float& d2, float& d3,
                                         unsigned a0, unsigned a1, unsigned a2, unsigned a3,
                                         unsigned b0, unsigned b1) {
    asm volatile(
        "mma.sync.aligned.m16n8k8.row.col.f32.tf32.tf32.f32 "
        "{%0,%1,%2,%3}, {%4,%5,%6,%7}, {%8,%9}, {%0,%1,%2,%3};"
        : "+f"(d0), "+f"(d1), "+f"(d2), "+f"(d3)
        : "r"(a0), "r"(a1), "r"(a2), "r"(a3), "r"(b0), "r"(b1));
}

__global__ void __launch_bounds__(NTHREADS)
gemm_kernel(const float* __restrict__ X,    // [16384, 768]
            const float* __restrict__ Wt,   // [768, 768]
            float* __restrict__ out)        // [16384, 768]
{
    __shared__ unsigned As[2][BM][BK + 1];       // 2 x [128][17]   = 17408 B
    __shared__ unsigned Bs[2][BK][BSTRIDE];      // 2 x [16][136]   = 17408 B

    const int tid   = threadIdx.x;
    const int wid   = tid >> 5;
    const int lane  = tid & 31;
    const int warp_m = wid & 3;           // 0..3 -> 32-row slice
    const int warp_n = wid >> 2;          // 0..1 -> 64-col slice
    const int g  = lane >> 2;             // groupID
    const int tg = lane & 3;              // threadID_in_group

    const int bm0 = blockIdx.x * BM;      // global M base
    const int bn0 = blockIdx.y * BN;      // global N base
    const int batch = bm0 >> 11;          // 128 | 2048 -> whole CTA in one batch

    // Per-thread load coordinates (fixed across iterations)
    const int a_row0 = tid >> 2;                  // 0..63
    const int a_c4   = tid & 3;                   // 0..3
    const int b_kr0  = tid >> 5;                  // 0..7
    const int b_c4   = tid & 31;                  // 0..31

    const float* Aptr0 = X  + (size_t)(bm0 + a_row0)      * DDIM + a_c4 * 4;
    const float* Aptr1 = X  + (size_t)(bm0 + a_row0 + 64) * DDIM + a_c4 * 4;
    const float* Bptr0 = Wt + (size_t)b_kr0               * DDIM + bn0 + b_c4 * 4;
    const float* Bptr1 = Wt + (size_t)(b_kr0 + 8)         * DDIM + bn0 + b_c4 * 4;

    float acc[2][8][4];
#pragma unroll
    for (int mt = 0; mt < 2; mt++)
#pragma unroll
        for (int nt = 0; nt < 8; nt++)
#pragma unroll
            for (int r = 0; r < 4; r++) acc[mt][nt][r] = 0.0f;

    // ---- prologue: load K-tile 0 into buffer 0 ----
    {
        float4 va0 = *reinterpret_cast<const float4*>(Aptr0);
        float4 va1 = *reinterpret_cast<const float4*>(Aptr1);
        float4 vb0 = *reinterpret_cast<const float4*>(Bptr0);
        float4 vb1 = *reinterpret_cast<const float4*>(Bptr1);
        As[0][a_row0     ][a_c4 * 4 + 0] = f2tf32(va0.x);
        As[0][a_row0     ][a_c4 * 4 + 1] = f2tf32(va0.y);
        As[0][a_row0     ][a_c4 * 4 + 2] = f2tf32(va0.z);
        As[0][a_row0     ][a_c4 * 4 + 3] = f2tf32(va0.w);
        As[0][a_row0 + 64][a_c4 * 4 + 0] = f2tf32(va1.x);
        As[0][a_row0 + 64][a_c4 * 4 + 1] = f2tf32(va1.y);
        As[0][a_row0 + 64][a_c4 * 4 + 2] = f2tf32(va1.z);
        As[0][a_row0 + 64][a_c4 * 4 + 3] = f2tf32(va1.w);
        Bs[0][b_kr0    ][b_c4 * 4 + 0] = f2tf32(vb0.x);
        Bs[0][b_kr0    ][b_c4 * 4 + 1] = f2tf32(vb0.y);
        Bs[0][b_kr0    ][b_c4 * 4 + 2] = f2tf32(vb0.z);
        Bs[0][b_kr0    ][b_c4 * 4 + 3] = f2tf32(vb0.w);
        Bs[0][b_kr0 + 8][b_c4 * 4 + 0] = f2tf32(vb1.x);
        Bs[0][b_kr0 + 8][b_c4 * 4 + 1] = f2tf32(vb1.y);
        Bs[0][b_kr0 + 8][b_c4 * 4 + 2] = f2tf32(vb1.z);
        Bs[0][b_kr0 + 8][b_c4 * 4 + 3] = f2tf32(vb1.w);
    }
    __syncthreads();

    for (int t = 0; t < KTILES; t++) {
        const int cur = t & 1;
        const int nxt = cur ^ 1;
        const bool has_next = (t + 1 < KTILES);

        // ---- issue next-tile global loads (latency hidden behind MMAs) ----
        float4 va0, va1, vb0, vb1;
        if (has_next) {
            const int k0n = (t + 1) * BK;
            va0 = *reinterpret_cast<const float4*>(Aptr0 + k0n);
            va1 = *reinterpret_cast<const float4*>(Aptr1 + k0n);
            vb0 = *reinterpret_cast<const float4*>(Bptr0 + (size_t)k0n * DDIM);
            vb1 = *reinterpret_cast<const float4*>(Bptr1 + (size_t)k0n * DDIM);
        }

        // ---- compute on current buffer ----
#pragma unroll
        for (int ks = 0; ks < 2; ks++) {
            const int kk = ks * 8;
            unsigned afr[2][4];
            unsigned bfr[8][2];
#pragma unroll
            for (int mt = 0; mt < 2; mt++) {
                int r = warp_m * 32 + mt * 16;
                afr[mt][0] = As[cur][r + g     ][kk + tg    ];
                afr[mt][1] = As[cur][r + g + 8 ][kk + tg    ];
                afr[mt][2] = As[cur][r + g     ][kk + tg + 4];
                afr[mt][3] = As[cur][r + g + 8 ][kk + tg + 4];
            }
#pragma unroll
            for (int nt = 0; nt < 8; nt++) {
                int c = warp_n * 64 + nt * 8 + g;
                bfr[nt][0] = Bs[cur][kk + tg    ][c];
                bfr[nt][1] = Bs[cur][kk + tg + 4][c];
            }
#pragma unroll
            for (int mt = 0; mt < 2; mt++)
#pragma unroll
                for (int nt = 0; nt < 8; nt++)
                    mma_tf32(acc[mt][nt][0], acc[mt][nt][1], acc[mt][nt][2], acc[mt][nt][3],
                             afr[mt][0], afr[mt][1], afr[mt][2], afr[mt][3],
                             bfr[nt][0], bfr[nt][1]);
        }

        // ---- stage next tile into the other buffer ----
        if (has_next) {
            As[nxt][a_row0     ][a_c4 * 4 + 0] = f2tf32(va0.x);
            As[nxt][a_row0     ][a_c4 * 4 + 1] = f2tf32(va0.y);
            As[nxt][a_row0     ][a_c4 * 4 + 2] = f2tf32(va0.z);
            As[nxt][a_row0     ][a_c4 * 4 + 3] = f2tf32(va0.w);
            As[nxt][a_row0 + 64][a_c4 * 4 + 0] = f2tf32(va1.x);
            As[nxt][a_row0 + 64][a_c4 * 4 + 1] = f2tf32(va1.y);
            As[nxt][a_row0 + 64][a_c4 * 4 + 2] = f2tf32(va1.z);
            As[nxt][a_row0 + 64][a_c4 * 4 + 3] = f2tf32(va1.w);
            Bs[nxt][b_kr0    ][b_c4 * 4 + 0] = f2tf32(vb0.x);
            Bs[nxt][b_kr0    ][b_c4 * 4 + 1] = f2tf32(vb0.y);
            Bs[nxt][b_kr0    ][b_c4 * 4 + 2] = f2tf32(vb0.z);
            Bs[nxt][b_kr0    ][b_c4 * 4 + 3] = f2tf32(vb0.w);
            Bs[nxt][b_kr0 + 8][b_c4 * 4 + 0] = f2tf32(vb1.x);
            Bs[nxt][b_kr0 + 8][b_c4 * 4 + 1] = f2tf32(vb1.y);
            Bs[nxt][b_kr0 + 8][b_c4 * 4 + 2] = f2tf32(vb1.z);
            Bs[nxt][b_kr0 + 8][b_c4 * 4 + 3] = f2tf32(vb1.w);
        }
        __syncthreads();
    }

    // ---- epilogue: add per-batch bias, write fp32 ----
#pragma unroll
    for (int mt = 0; mt < 2; mt++) {
#pragma unroll
        for (int nt = 0; nt < 8; nt++) {
            int m = bm0 + warp_m * 32 + mt * 16 + g;
            int n = bn0 + warp_n * 64 + nt * 8 + 2 * tg;
            float b0 = g_bias[batch][n];
            float b1 = g_bias[batch][n + 1];
            float2 v0 = make_float2(acc[mt][nt][0] + b0, acc[mt][nt][1] + b1);
            float2 v1 = make_float2(acc[mt][nt][2] + b0, acc[mt][nt][3] + b1);
            *reinterpret_cast<float2*>(out + (size_t)m * DDIM + n) = v0;
            *reinterpret_cast<float2*>(out + (size_t)(m + 8) * DDIM + n) = v1;
        }
    }
}

// ---------------------------------------------------------------------------
// Launch
// ---------------------------------------------------------------------------
extern "C" void kernel_launch(void* const* d_in, const int* in_sizes, int n_in,
                              void* d_out, int out_size) {
    const float* X  = (const float*)d_in[0];   // text_features [8,2048,768]
    const float* ac = (const float*)d_in[1];   // acoustic_features [8,16]
    const float* Wt = (const float*)d_in[2];   // [768,768]
    const float* bt = (const float*)d_in[3];   // [768]
    const float* Wa = (const float*)d_in[4];   // [16,768]
    const float* ba = (const float*)d_in[5];   // [768]
    // d_in[6..9] = Wq, bq, Wk, bk — provably unused (softmax over constant scores is uniform)
    const float* Wv = (const float*)d_in[10];  // [768,768]
    const float* bv = (const float*)d_in[11];  // [768]
    float* out = (float*)d_out;

    bias_kernel<<<BATCH, DDIM>>>(ac, Wa, ba, Wv, bv, bt);

    dim3 grid(MTOT / BM, DDIM / BN);           // (128, 6)
    gemm_kernel<<<grid, NTHREADS>>>(X, Wt, out);
}